// round 1
// baseline (speedup 1.0000x reference)
#include <cuda_runtime.h>
#include <cuda_bf16.h>

#define U      128
#define TT     96
#define NIN    6
#define NUNF   6
#define MOTOR  64
#define NCLS   100
#define BATCH  1024
#define NG     (BATCH/4)
#define LOG2E  1.4426950408889634f
#define EPSF   1e-8f

// ---------------- scratch (device globals; no allocation allowed) ----------
__device__ float4 g_syn[U*U];          // per target u: up to U entries (A, B, wp, wp*erev)
__device__ int    g_jidx[U*U];         // source index per entry
__device__ int    g_cnt[U];
__device__ float  g_cmt[U], g_gl[U], g_glv[U];
__device__ float4 g_sensw[NIN*U];      // sensory (A, B, swp, swp*erev)
__device__ float4 g_snum[NG*TT*U];     // sensory numerator sums, float4 over 4 batches
__device__ float4 g_sden[NG*TT*U];
__device__ float  g_outs[BATCH*TT*MOTOR];

__device__ __forceinline__ float fast_ex2(float x){ float y; asm("ex2.approx.ftz.f32 %0, %1;" : "=f"(y) : "f"(x)); return y; }
__device__ __forceinline__ float fast_rcp(float x){ float y; asm("rcp.approx.ftz.f32 %0, %1;" : "=f"(y) : "f"(x)); return y; }
__device__ __forceinline__ float softplusf(float x){ return (x > 20.f) ? x : log1pf(expf(x)); }

// ---------------- prep: constant folding + CSR build -----------------------
__global__ void prep_kernel(const float* gleak, const float* vleak, const float* cm,
                            const float* sigma, const float* mu, const float* w,
                            const float* erev, const float* ss, const float* smu,
                            const float* sw, const float* serev,
                            const float* mask, const float* smask)
{
    int u = threadIdx.x;
    g_cmt[u] = softplusf(cm[u]) * (float)NUNF;
    float gl = softplusf(gleak[u]);
    g_gl[u]  = gl;
    g_glv[u] = gl * vleak[u];

    int cnt = 0;
    for (int j = 0; j < U; j++) {
        float m = mask[j*U + u];
        if (m != 0.f) {
            float sg  = sigma[j*U + u];
            float wp  = softplusf(w[j*U + u]) * m;
            float4 e;
            e.x = -sg * LOG2E;                 // A (negated, folded log2e)
            e.y = mu[j*U + u] * sg * LOG2E;    // B
            e.z = wp;
            e.w = wp * erev[j*U + u];
            g_syn[u*U + cnt]  = e;
            g_jidx[u*U + cnt] = j;
            cnt++;
        }
    }
    g_cnt[u] = cnt;

    for (int i = 0; i < NIN; i++) {
        float m  = smask[i*U + u];
        float sg = ss[i*U + u];
        float wp = softplusf(sw[i*U + u]) * m;
        float4 e;
        e.x = -sg * LOG2E;
        e.y = smu[i*U + u] * sg * LOG2E;
        e.z = wp;
        e.w = wp * serev[i*U + u];
        g_sensw[i*U + u] = e;
    }
}

// ---------------- sensory precompute: LayerNorm + sensory synapse sums -----
__global__ void sens_kernel(const float* __restrict__ x, const float* __restrict__ ln_g,
                            const float* __restrict__ ln_b, const float* __restrict__ in_w,
                            const float* __restrict__ in_b)
{
    int t = blockIdx.x;
    int b = blockIdx.y;
    int u = threadIdx.x;

    const float* xp = x + (b*TT + t)*NIN;
    float xv[NIN];
    float mean = 0.f;
    #pragma unroll
    for (int i = 0; i < NIN; i++) { xv[i] = xp[i]; mean += xv[i]; }
    mean *= (1.f/NIN);
    float var = 0.f;
    #pragma unroll
    for (int i = 0; i < NIN; i++) { float d = xv[i] - mean; var += d*d; }
    var *= (1.f/NIN);
    float inv = rsqrtf(var + 1e-5f);

    float inp[NIN];
    #pragma unroll
    for (int i = 0; i < NIN; i++)
        inp[i] = ((xv[i]-mean)*inv*ln_g[i] + ln_b[i]) * in_w[i] + in_b[i];

    float num = 0.f, den = 0.f;
    #pragma unroll
    for (int i = 0; i < NIN; i++) {
        float4 S = g_sensw[i*U + u];
        float e = fast_ex2(fmaf(inp[i], S.x, S.y));
        float r = fast_rcp(1.f + e);
        num = fmaf(S.w, r, num);
        den = fmaf(S.z, r, den);
    }
    int g = b >> 2, lane = b & 3;
    int idx = ((g*TT + t)*U + u)*4 + lane;
    ((float*)g_snum)[idx] = num;
    ((float*)g_sden)[idx] = den;
}

// ---------------- main LTC recurrence --------------------------------------
__global__ void __launch_bounds__(U) ltc_main(const float* __restrict__ out_w,
                                              const float* __restrict__ out_b)
{
    __shared__ float4 vbuf[2][U];
    int u = threadIdx.x;
    int g = blockIdx.x;

    float cmt = g_cmt[u], gl = g_gl[u], glv = g_glv[u];
    int cnt = g_cnt[u];
    const float4* __restrict__ syn  = g_syn  + u*U;
    const int*    __restrict__ jidx = g_jidx + u*U;

    float ow = 0.f, ob = 0.f;
    if (u < MOTOR) { ow = out_w[u]; ob = out_b[u]; }

    vbuf[0][u] = make_float4(0.f, 0.f, 0.f, 0.f);
    __syncthreads();
    int cur = 0;

    const float4* __restrict__ snum = g_snum + g*TT*U;
    const float4* __restrict__ sden = g_sden + g*TT*U;
    float dc = cmt + gl;

    for (int t = 0; t < TT; t++) {
        float4 sn = snum[t*U + u];
        float4 sd = sden[t*U + u];
        float bnx = glv + sn.x, bny = glv + sn.y, bnz = glv + sn.z, bnw = glv + sn.w;
        float bdx = dc + sd.x,  bdy = dc + sd.y,  bdz = dc + sd.z,  bdw = dc + sd.w;

        #pragma unroll 1
        for (int f = 0; f < NUNF; f++) {
            float4 vu = vbuf[cur][u];
            float nx = fmaf(cmt, vu.x, bnx);
            float ny = fmaf(cmt, vu.y, bny);
            float nz = fmaf(cmt, vu.z, bnz);
            float nw = fmaf(cmt, vu.w, bnw);
            float dx = bdx, dy = bdy, dz = bdz, dw = bdw;

            for (int k = 0; k < cnt; k++) {
                int j = jidx[k];
                float4 W  = syn[k];
                float4 vj = vbuf[cur][j];
                float e0 = fast_ex2(fmaf(vj.x, W.x, W.y));
                float e1 = fast_ex2(fmaf(vj.y, W.x, W.y));
                float e2 = fast_ex2(fmaf(vj.z, W.x, W.y));
                float e3 = fast_ex2(fmaf(vj.w, W.x, W.y));
                float r0 = fast_rcp(1.f + e0);
                float r1 = fast_rcp(1.f + e1);
                float r2 = fast_rcp(1.f + e2);
                float r3 = fast_rcp(1.f + e3);
                nx = fmaf(W.w, r0, nx); dx = fmaf(W.z, r0, dx);
                ny = fmaf(W.w, r1, ny); dy = fmaf(W.z, r1, dy);
                nz = fmaf(W.w, r2, nz); dz = fmaf(W.z, r2, dz);
                nw = fmaf(W.w, r3, nw); dw = fmaf(W.z, r3, dw);
            }
            float4 vn;
            vn.x = nx * fast_rcp(dx + EPSF);
            vn.y = ny * fast_rcp(dy + EPSF);
            vn.z = nz * fast_rcp(dz + EPSF);
            vn.w = nw * fast_rcp(dw + EPSF);
            vbuf[cur ^ 1][u] = vn;
            __syncthreads();
            cur ^= 1;
        }

        if (u < MOTOR) {
            float4 vv = vbuf[cur][u];
            int b0 = g * 4;
            g_outs[((b0+0)*TT + t)*MOTOR + u] = fmaf(vv.x, ow, ob);
            g_outs[((b0+1)*TT + t)*MOTOR + u] = fmaf(vv.y, ow, ob);
            g_outs[((b0+2)*TT + t)*MOTOR + u] = fmaf(vv.z, ow, ob);
            g_outs[((b0+3)*TT + t)*MOTOR + u] = fmaf(vv.w, ow, ob);
        }
    }
}

// ---------------- attention pooling + classifier ----------------------------
__global__ void __launch_bounds__(128) attn_kernel(
    const float* __restrict__ aw1, const float* __restrict__ ab1,
    const float* __restrict__ aw2, const float* __restrict__ cw1,
    const float* __restrict__ cb1, const float* __restrict__ cw2,
    const float* __restrict__ cb2, float* __restrict__ out)
{
    __shared__ float so[TT][MOTOR+1];   // +1 pad: kill stride-64 bank conflicts
    __shared__ float w1[MOTOR*32];
    __shared__ float sc[TT];
    __shared__ float ctx[MOTOR];
    __shared__ float hid[128];

    int b = blockIdx.x, tid = threadIdx.x;

    for (int i = tid; i < TT*MOTOR; i += 128)
        so[i/MOTOR][i%MOTOR] = g_outs[b*TT*MOTOR + i];
    for (int i = tid; i < MOTOR*32; i += 128)
        w1[i] = aw1[i];
    __syncthreads();

    if (tid < TT) {
        float acc = 0.f;
        for (int h = 0; h < 32; h++) {
            float s = ab1[h];
            #pragma unroll 8
            for (int uu = 0; uu < MOTOR; uu++)
                s = fmaf(so[tid][uu], w1[uu*32 + h], s);
            s = fmaxf(s, 0.f);
            acc = fmaf(s, aw2[h], acc);
        }
        sc[tid] = acc;
    }
    __syncthreads();

    if (tid == 0) {
        float m = -1e30f;
        for (int t = 0; t < TT; t++) m = fmaxf(m, sc[t]);
        float s = 0.f;
        for (int t = 0; t < TT; t++) { float e = __expf(sc[t]-m); sc[t] = e; s += e; }
        float invs = 1.f / s;
        for (int t = 0; t < TT; t++) sc[t] *= invs;
    }
    __syncthreads();

    if (tid < MOTOR) {
        float a = 0.f;
        for (int t = 0; t < TT; t++) a = fmaf(sc[t], so[t][tid], a);
        ctx[tid] = a;
    }
    __syncthreads();

    {
        float s = cb1[tid];
        for (int uu = 0; uu < MOTOR; uu++)
            s = fmaf(ctx[uu], cw1[uu*128 + tid], s);
        hid[tid] = fmaxf(s, 0.f);
    }
    __syncthreads();

    if (tid < NCLS) {
        float s = cb2[tid];
        for (int h = 0; h < 128; h++)
            s = fmaf(hid[h], cw2[h*NCLS + tid], s);
        out[b*NCLS + tid] = s;
    }
}

// ---------------- launch ----------------------------------------------------
extern "C" void kernel_launch(void* const* d_in, const int* in_sizes, int n_in,
                              void* d_out, int out_size)
{
    const float* x        = (const float*)d_in[0];
    const float* ln_g     = (const float*)d_in[1];
    const float* ln_b     = (const float*)d_in[2];
    const float* gleak    = (const float*)d_in[3];
    const float* vleak    = (const float*)d_in[4];
    const float* cm       = (const float*)d_in[5];
    const float* sigma    = (const float*)d_in[6];
    const float* mu       = (const float*)d_in[7];
    const float* w        = (const float*)d_in[8];
    const float* erev     = (const float*)d_in[9];
    const float* ssig     = (const float*)d_in[10];
    const float* smu      = (const float*)d_in[11];
    const float* sw       = (const float*)d_in[12];
    const float* serev    = (const float*)d_in[13];
    const float* in_w     = (const float*)d_in[14];
    const float* in_b     = (const float*)d_in[15];
    const float* out_w    = (const float*)d_in[16];
    const float* out_b    = (const float*)d_in[17];
    const float* aw1      = (const float*)d_in[18];
    const float* ab1      = (const float*)d_in[19];
    const float* aw2      = (const float*)d_in[20];
    const float* cw1      = (const float*)d_in[21];
    const float* cb1      = (const float*)d_in[22];
    const float* cw2      = (const float*)d_in[23];
    const float* cb2      = (const float*)d_in[24];
    const float* mask     = (const float*)d_in[25];
    const float* smask    = (const float*)d_in[26];

    prep_kernel<<<1, U>>>(gleak, vleak, cm, sigma, mu, w, erev,
                          ssig, smu, sw, serev, mask, smask);
    sens_kernel<<<dim3(TT, BATCH), U>>>(x, ln_g, ln_b, in_w, in_b);
    ltc_main<<<NG, U>>>(out_w, out_b);
    attn_kernel<<<BATCH, 128>>>(aw1, ab1, aw2, cw1, cb1, cw2, cb2, (float*)d_out);
}

// round 2
// speedup vs baseline: 4.0360x; 4.0360x over previous
#include <cuda_runtime.h>
#include <cuda_bf16.h>

#define U      128
#define TT     96
#define NIN    6
#define NUNF   6
#define MOTOR  64
#define NCLS   100
#define BATCH  1024
#define NG     (BATCH/4)
#define LOG2E  1.4426950408889634f
#define EPSF   1e-8f

// ---------------- scratch (device globals; no allocation allowed) ----------
// Transposed synapse tables: entry for (k, target-slot s) at [k*U + s].
// Warp lanes (consecutive s) read consecutive entries -> coalesced LDG.
__device__ float4 g_synT[U*U];         // (A, B, wp, wp*erev)
__device__ int    g_jT[U*U];           // source SLOT index
__device__ int    g_scnt[U];           // per-slot nnz
__device__ int    g_perm[U];           // slot -> original unit
__device__ int    g_inv[U];            // original unit -> slot
__device__ float  g_cmt[U], g_gl[U], g_glv[U];   // per-slot constants
__device__ float4 g_sensw[NIN*U];      // sensory (A, B, swp, swp*erev), unit-indexed
__device__ float4 g_snum[NG*TT*U];     // sensory sums, slot-indexed, float4 = 4 batches
__device__ float4 g_sden[NG*TT*U];
__device__ float  g_outs[BATCH*TT*MOTOR];

__device__ __forceinline__ float fast_ex2(float x){ float y; asm("ex2.approx.ftz.f32 %0, %1;" : "=f"(y) : "f"(x)); return y; }
__device__ __forceinline__ float fast_rcp(float x){ float y; asm("rcp.approx.ftz.f32 %0, %1;" : "=f"(y) : "f"(x)); return y; }
__device__ __forceinline__ float softplusf(float x){ return (x > 20.f) ? x : log1pf(expf(x)); }

// ---------------- prep: constant folding + sorted-CSR (transposed) ---------
__global__ void prep_kernel(const float* gleak, const float* vleak, const float* cm,
                            const float* sigma, const float* mu, const float* w,
                            const float* erev, const float* ss, const float* smu,
                            const float* sw, const float* serev,
                            const float* mask, const float* smask)
{
    __shared__ int scnt[U];
    __shared__ int sinv[U];
    int u = threadIdx.x;

    // count nonzeros targeting unit u
    int cnt = 0;
    for (int j = 0; j < U; j++)
        if (mask[j*U + u] != 0.f) cnt++;
    scnt[u] = cnt;
    __syncthreads();

    // rank by cnt (stable): slot index for this unit
    int r = 0;
    for (int v = 0; v < U; v++) {
        int c = scnt[v];
        if (c < cnt || (c == cnt && v < u)) r++;
    }
    sinv[u] = r;
    __syncthreads();

    g_perm[r] = u;
    g_inv[u]  = r;
    g_scnt[r] = cnt;
    g_cmt[r]  = softplusf(cm[u]) * (float)NUNF;
    float gl  = softplusf(gleak[u]);
    g_gl[r]   = gl;
    g_glv[r]  = gl * vleak[u];

    // build transposed table at slot r
    int k = 0;
    for (int j = 0; j < U; j++) {
        float m = mask[j*U + u];
        if (m != 0.f) {
            float sg  = sigma[j*U + u];
            float wp  = softplusf(w[j*U + u]) * m;
            float4 e;
            e.x = -sg * LOG2E;
            e.y = mu[j*U + u] * sg * LOG2E;
            e.z = wp;
            e.w = wp * erev[j*U + u];
            g_synT[k*U + r] = e;
            g_jT[k*U + r]   = sinv[j];   // source slot
            k++;
        }
    }

    // sensory weights stay unit-indexed (sens_kernel remaps to slots on write)
    for (int i = 0; i < NIN; i++) {
        float m  = smask[i*U + u];
        float sg = ss[i*U + u];
        float wp = softplusf(sw[i*U + u]) * m;
        float4 e;
        e.x = -sg * LOG2E;
        e.y = smu[i*U + u] * sg * LOG2E;
        e.z = wp;
        e.w = wp * serev[i*U + u];
        g_sensw[i*U + u] = e;
    }
}

// ---------------- sensory precompute: LayerNorm + sensory synapse sums -----
__global__ void sens_kernel(const float* __restrict__ x, const float* __restrict__ ln_g,
                            const float* __restrict__ ln_b, const float* __restrict__ in_w,
                            const float* __restrict__ in_b)
{
    int t = blockIdx.x;
    int b = blockIdx.y;
    int u = threadIdx.x;

    const float* xp = x + (b*TT + t)*NIN;
    float xv[NIN];
    float mean = 0.f;
    #pragma unroll
    for (int i = 0; i < NIN; i++) { xv[i] = xp[i]; mean += xv[i]; }
    mean *= (1.f/NIN);
    float var = 0.f;
    #pragma unroll
    for (int i = 0; i < NIN; i++) { float d = xv[i] - mean; var += d*d; }
    var *= (1.f/NIN);
    float inv = rsqrtf(var + 1e-5f);

    float inp[NIN];
    #pragma unroll
    for (int i = 0; i < NIN; i++)
        inp[i] = ((xv[i]-mean)*inv*ln_g[i] + ln_b[i]) * in_w[i] + in_b[i];

    float num = 0.f, den = 0.f;
    #pragma unroll
    for (int i = 0; i < NIN; i++) {
        float4 S = g_sensw[i*U + u];
        float e = fast_ex2(fmaf(inp[i], S.x, S.y));
        float r = fast_rcp(1.f + e);
        num = fmaf(S.w, r, num);
        den = fmaf(S.z, r, den);
    }
    int slot = g_inv[u];
    int g = b >> 2, lane = b & 3;
    int idx = ((g*TT + t)*U + slot)*4 + lane;
    ((float*)g_snum)[idx] = num;
    ((float*)g_sden)[idx] = den;
}

// ---------------- main LTC recurrence --------------------------------------
__global__ void __launch_bounds__(U) ltc_main(const float* __restrict__ out_w,
                                              const float* __restrict__ out_b)
{
    __shared__ float4 vbuf[2][U];
    __shared__ float s_ow[MOTOR], s_ob[MOTOR];
    __shared__ int   s_mslot[MOTOR];    // slot holding motor unit m

    int u = threadIdx.x;     // slot index
    int g = blockIdx.x;

    float cmt = g_cmt[u], gl = g_gl[u], glv = g_glv[u];
    int cnt = g_scnt[u];

    if (u < MOTOR) {
        s_ow[u] = out_w[u];
        s_ob[u] = out_b[u];
        s_mslot[u] = g_inv[u];
    }

    vbuf[0][u] = make_float4(0.f, 0.f, 0.f, 0.f);
    __syncthreads();
    int cur = 0;

    const float4* __restrict__ snum = g_snum + g*TT*U;
    const float4* __restrict__ sden = g_sden + g*TT*U;
    float dc = cmt + gl;

    int m  = u & 63;          // motor unit for output stage
    int q  = u >> 6;          // batch-quad lane pair (0 or 1)
    int b0 = g * 4;

    for (int t = 0; t < TT; t++) {
        float4 sn = snum[t*U + u];
        float4 sd = sden[t*U + u];
        float bnx = glv + sn.x, bny = glv + sn.y, bnz = glv + sn.z, bnw = glv + sn.w;
        float bdx = dc + sd.x,  bdy = dc + sd.y,  bdz = dc + sd.z,  bdw = dc + sd.w;

        #pragma unroll 1
        for (int f = 0; f < NUNF; f++) {
            float4 vu = vbuf[cur][u];
            float nx = fmaf(cmt, vu.x, bnx);
            float ny = fmaf(cmt, vu.y, bny);
            float nz = fmaf(cmt, vu.z, bnz);
            float nw = fmaf(cmt, vu.w, bnw);
            float dx = bdx, dy = bdy, dz = bdz, dw = bdw;

            for (int k = 0; k < cnt; k++) {
                float4 W  = __ldg(&g_synT[k*U + u]);   // coalesced, L1-resident
                int    j  = __ldg(&g_jT  [k*U + u]);   // coalesced
                float4 vj = vbuf[cur][j];
                float e0 = fast_ex2(fmaf(vj.x, W.x, W.y));
                float e1 = fast_ex2(fmaf(vj.y, W.x, W.y));
                float e2 = fast_ex2(fmaf(vj.z, W.x, W.y));
                float e3 = fast_ex2(fmaf(vj.w, W.x, W.y));
                float r0 = fast_rcp(1.f + e0);
                float r1 = fast_rcp(1.f + e1);
                float r2 = fast_rcp(1.f + e2);
                float r3 = fast_rcp(1.f + e3);
                nx = fmaf(W.w, r0, nx); dx = fmaf(W.z, r0, dx);
                ny = fmaf(W.w, r1, ny); dy = fmaf(W.z, r1, dy);
                nz = fmaf(W.w, r2, nz); dz = fmaf(W.z, r2, dz);
                nw = fmaf(W.w, r3, nw); dw = fmaf(W.z, r3, dw);
            }
            float4 vn;
            vn.x = nx * fast_rcp(dx + EPSF);
            vn.y = ny * fast_rcp(dy + EPSF);
            vn.z = nz * fast_rcp(dz + EPSF);
            vn.w = nw * fast_rcp(dw + EPSF);
            vbuf[cur ^ 1][u] = vn;
            __syncthreads();
            cur ^= 1;
        }

        // coalesced motor-output write: thread -> (quad q / q+2, motor unit m)
        {
            float4 vv = vbuf[cur][s_mslot[m]];   // LDS gather (small conflicts)
            float o0 = (q == 0) ? vv.x : vv.y;
            float o1 = (q == 0) ? vv.z : vv.w;
            float ww = s_ow[m], bb = s_ob[m];
            g_outs[((b0 + q    )*TT + t)*MOTOR + m] = fmaf(o0, ww, bb);
            g_outs[((b0 + q + 2)*TT + t)*MOTOR + m] = fmaf(o1, ww, bb);
        }
        // vbuf[cur] is read here; next overwrite of vbuf[cur] is after the
        // next unfold's __syncthreads, so no extra barrier is needed.
    }
}

// ---------------- attention pooling + classifier ----------------------------
__global__ void __launch_bounds__(128) attn_kernel(
    const float* __restrict__ aw1, const float* __restrict__ ab1,
    const float* __restrict__ aw2, const float* __restrict__ cw1,
    const float* __restrict__ cb1, const float* __restrict__ cw2,
    const float* __restrict__ cb2, float* __restrict__ out)
{
    __shared__ float so[TT][MOTOR+1];   // +1 pad: kill stride-64 bank conflicts
    __shared__ float w1[MOTOR*32];
    __shared__ float sc[TT];
    __shared__ float ctx[MOTOR];
    __shared__ float hid[128];

    int b = blockIdx.x, tid = threadIdx.x;

    for (int i = tid; i < TT*MOTOR; i += 128)
        so[i/MOTOR][i%MOTOR] = g_outs[b*TT*MOTOR + i];
    for (int i = tid; i < MOTOR*32; i += 128)
        w1[i] = aw1[i];
    __syncthreads();

    if (tid < TT) {
        float acc = 0.f;
        for (int h = 0; h < 32; h++) {
            float s = ab1[h];
            #pragma unroll 8
            for (int uu = 0; uu < MOTOR; uu++)
                s = fmaf(so[tid][uu], w1[uu*32 + h], s);
            s = fmaxf(s, 0.f);
            acc = fmaf(s, aw2[h], acc);
        }
        sc[tid] = acc;
    }
    __syncthreads();

    if (tid == 0) {
        float m = -1e30f;
        for (int t = 0; t < TT; t++) m = fmaxf(m, sc[t]);
        float s = 0.f;
        for (int t = 0; t < TT; t++) { float e = __expf(sc[t]-m); sc[t] = e; s += e; }
        float invs = 1.f / s;
        for (int t = 0; t < TT; t++) sc[t] *= invs;
    }
    __syncthreads();

    if (tid < MOTOR) {
        float a = 0.f;
        for (int t = 0; t < TT; t++) a = fmaf(sc[t], so[t][tid], a);
        ctx[tid] = a;
    }
    __syncthreads();

    {
        float s = cb1[tid];
        for (int uu = 0; uu < MOTOR; uu++)
            s = fmaf(ctx[uu], cw1[uu*128 + tid], s);
        hid[tid] = fmaxf(s, 0.f);
    }
    __syncthreads();

    if (tid < NCLS) {
        float s = cb2[tid];
        for (int h = 0; h < 128; h++)
            s = fmaf(hid[h], cw2[h*NCLS + tid], s);
        out[b*NCLS + tid] = s;
    }
}

// ---------------- launch ----------------------------------------------------
extern "C" void kernel_launch(void* const* d_in, const int* in_sizes, int n_in,
                              void* d_out, int out_size)
{
    const float* x        = (const float*)d_in[0];
    const float* ln_g     = (const float*)d_in[1];
    const float* ln_b     = (const float*)d_in[2];
    const float* gleak    = (const float*)d_in[3];
    const float* vleak    = (const float*)d_in[4];
    const float* cm       = (const float*)d_in[5];
    const float* sigma    = (const float*)d_in[6];
    const float* mu       = (const float*)d_in[7];
    const float* w        = (const float*)d_in[8];
    const float* erev     = (const float*)d_in[9];
    const float* ssig     = (const float*)d_in[10];
    const float* smu      = (const float*)d_in[11];
    const float* sw       = (const float*)d_in[12];
    const float* serev    = (const float*)d_in[13];
    const float* in_w     = (const float*)d_in[14];
    const float* in_b     = (const float*)d_in[15];
    const float* out_w    = (const float*)d_in[16];
    const float* out_b    = (const float*)d_in[17];
    const float* aw1      = (const float*)d_in[18];
    const float* ab1      = (const float*)d_in[19];
    const float* aw2      = (const float*)d_in[20];
    const float* cw1      = (const float*)d_in[21];
    const float* cb1      = (const float*)d_in[22];
    const float* cw2      = (const float*)d_in[23];
    const float* cb2      = (const float*)d_in[24];
    const float* mask     = (const float*)d_in[25];
    const float* smask    = (const float*)d_in[26];

    prep_kernel<<<1, U>>>(gleak, vleak, cm, sigma, mu, w, erev,
                          ssig, smu, sw, serev, mask, smask);
    sens_kernel<<<dim3(TT, BATCH), U>>>(x, ln_g, ln_b, in_w, in_b);
    ltc_main<<<NG, U>>>(out_w, out_b);
    attn_kernel<<<BATCH, 128>>>(aw1, ab1, aw2, cw1, cb1, cw2, cb2, (float*)d_out);
}